// round 3
// baseline (speedup 1.0000x reference)
#include <cuda_runtime.h>
#include <cstdint>

#define D_MODEL 1024
#define HIDDEN  64
#define BATCH   8
#define SEQ     4096
#define ROWS    128     // M-tile per block
#define KC      32      // K chunk
#define XSTRIDE 36      // 32 + 4 pad (conflict-free frag reads)
#define YSTRIDE 68      // 64 + 4 pad

// Scratch (allocation-free rule: device globals)
__device__ float g_kbuf[BATCH * SEQ * HIDDEN];
__device__ float g_vbuf[BATCH * SEQ * HIDDEN];
__device__ float g_w[BATCH * HIDDEN];

__device__ __forceinline__ uint32_t f2tf(float x) {
    uint32_t r;
    asm("cvt.rna.tf32.f32 %0, %1;" : "=r"(r) : "f"(x));
    return r;
}

__device__ __forceinline__ void mma8(float c[4], const uint32_t a[4], const uint32_t b[2]) {
    asm volatile(
        "mma.sync.aligned.m16n8k8.row.col.f32.tf32.tf32.f32 "
        "{%0,%1,%2,%3}, {%4,%5,%6,%7}, {%8,%9}, {%0,%1,%2,%3};\n"
        : "+f"(c[0]), "+f"(c[1]), "+f"(c[2]), "+f"(c[3])
        : "r"(a[0]), "r"(a[1]), "r"(a[2]), "r"(a[3]), "r"(b[0]), "r"(b[1]));
}

// P[128x64] = X[baseRow:baseRow+128, 0:1024] @ W[64,1024]^T   (bias handled by caller)
// Accumulators: warp w owns rows [16w,16w+16); acc[nt] = n-tile nt (cols nt*8..nt*8+7).
__device__ __forceinline__ void proj64(const float* __restrict__ X,
                                       const float* __restrict__ W,
                                       int baseRow,
                                       uint32_t* Xs, uint32_t* Ws,
                                       float acc[8][4]) {
    const int tid  = threadIdx.x;
    const int warp = tid >> 5;
    const int lane = tid & 31;
    const int gid  = lane >> 2;
    const int ctid = lane & 3;

    for (int kc = 0; kc < D_MODEL; kc += KC) {
        // ---- stage X tile [128 x 32] and W tile [64 x 32] as tf32 ----
        {
            const int r  = tid >> 3;         // 0..31
            const int c4 = (tid & 7) * 4;    // 0,4,...,28
#pragma unroll
            for (int rr = 0; rr < 4; rr++) {
                const float4 v = *(const float4*)(X + (size_t)(baseRow + r + rr * 32) * D_MODEL + kc + c4);
                uint32_t* dst = Xs + (r + rr * 32) * XSTRIDE + c4;
                dst[0] = f2tf(v.x); dst[1] = f2tf(v.y); dst[2] = f2tf(v.z); dst[3] = f2tf(v.w);
            }
#pragma unroll
            for (int rr = 0; rr < 2; rr++) {
                const float4 v = *(const float4*)(W + (size_t)(r + rr * 32) * D_MODEL + kc + c4);
                uint32_t* dst = Ws + (r + rr * 32) * XSTRIDE + c4;
                dst[0] = f2tf(v.x); dst[1] = f2tf(v.y); dst[2] = f2tf(v.z); dst[3] = f2tf(v.w);
            }
        }
        __syncthreads();

        // ---- compute: 4 k8-steps, 8 n-tiles each ----
#pragma unroll
        for (int ks = 0; ks < KC / 8; ks++) {
            uint32_t a[4];
            const uint32_t* xrow = Xs + (warp * 16 + gid) * XSTRIDE + ks * 8 + ctid;
            a[0] = xrow[0];
            a[1] = xrow[8 * XSTRIDE];
            a[2] = xrow[4];
            a[3] = xrow[8 * XSTRIDE + 4];
#pragma unroll
            for (int nt = 0; nt < 8; nt++) {
                uint32_t b[2];
                const uint32_t* wrow = Ws + (nt * 8 + gid) * XSTRIDE + ks * 8 + ctid;
                b[0] = wrow[0];
                b[1] = wrow[4];
                mma8(acc[nt], a, b);
            }
        }
        __syncthreads();
    }
}

// ---------------- Kernel 1: k & v projections ----------------
__global__ void __launch_bounds__(256) kv_proj_kernel(
    const float* __restrict__ key_in, const float* __restrict__ value_in,
    const float* __restrict__ Wk, const float* __restrict__ bk,
    const float* __restrict__ Wv, const float* __restrict__ bv) {
    __shared__ uint32_t Xs[ROWS * XSTRIDE];
    __shared__ uint32_t Ws[HIDDEN * XSTRIDE];

    const int bx      = blockIdx.x;
    const int which   = bx >> 8;         // 0 -> k, 1 -> v
    const int baseRow = (bx & 255) * ROWS;

    const float* X    = which ? value_in : key_in;
    const float* W    = which ? Wv : Wk;
    const float* bias = which ? bv : bk;
    float* outb       = which ? g_vbuf : g_kbuf;

    float acc[8][4] = {};
    proj64(X, W, baseRow, Xs, Ws, acc);

    const int lane = threadIdx.x & 31, warp = threadIdx.x >> 5;
    const int gid = lane >> 2, ctid = lane & 3;
#pragma unroll
    for (int nt = 0; nt < 8; nt++) {
        const int col = nt * 8 + 2 * ctid;
        const float b0 = bias[col], b1 = bias[col + 1];
        const size_t r0 = (size_t)(baseRow + warp * 16 + gid);
        *(float2*)(outb + r0 * HIDDEN + col) = make_float2(acc[nt][0] + b0, acc[nt][1] + b1);
        *(float2*)(outb + (r0 + 8) * HIDDEN + col) = make_float2(acc[nt][2] + b0, acc[nt][3] + b1);
    }
}

// ---------------- Kernel 2: softmax-weighted pooling ----------------
__global__ void __launch_bounds__(256) reduce_kernel() {
    const int b = blockIdx.x >> 6;
    const int h = blockIdx.x & 63;
    const int tid = threadIdx.x;
    const int lane = tid & 31;
    const int warp = tid >> 5;
    const float* kcol = g_kbuf + (size_t)b * SEQ * HIDDEN + h;
    const float* vcol = g_vbuf + (size_t)b * SEQ * HIDDEN + h;

    __shared__ float redm[8];
    __shared__ float reds[8];
    __shared__ float redw[8];

    // pass 1: max
    float m = -1e30f;
    for (int n = tid; n < SEQ; n += 256) m = fmaxf(m, kcol[(size_t)n * HIDDEN]);
#pragma unroll
    for (int s = 16; s > 0; s >>= 1) m = fmaxf(m, __shfl_xor_sync(0xffffffffu, m, s));
    if (lane == 0) redm[warp] = m;
    __syncthreads();
    {
        float mm = redm[0];
#pragma unroll
        for (int w = 1; w < 8; w++) mm = fmaxf(mm, redm[w]);
        m = mm;
    }

    // pass 2: sumexp + weighted sum
    float se = 0.f, ws = 0.f;
    for (int n = tid; n < SEQ; n += 256) {
        const float e = __expf(kcol[(size_t)n * HIDDEN] - m);
        se += e;
        ws += e * vcol[(size_t)n * HIDDEN];
    }
#pragma unroll
    for (int s = 16; s > 0; s >>= 1) {
        se += __shfl_xor_sync(0xffffffffu, se, s);
        ws += __shfl_xor_sync(0xffffffffu, ws, s);
    }
    if (lane == 0) { reds[warp] = se; redw[warp] = ws; }
    __syncthreads();
    if (tid == 0) {
        float tse = reds[0], tws = redw[0];
#pragma unroll
        for (int w = 1; w < 8; w++) { tse += reds[w]; tws += redw[w]; }
        g_w[b * HIDDEN + h] = tws / tse;
    }
}

// ---------------- Kernel 3: fused q-proj -> sigmoid*weights -> Wp proj ----------------
__global__ void __launch_bounds__(256) out_kernel(
    const float* __restrict__ query, const float* __restrict__ Wq,
    const float* __restrict__ bq, const float* __restrict__ Wp,
    const float* __restrict__ bp, float* __restrict__ out) {
    extern __shared__ uint32_t smem[];
    uint32_t* Xs  = smem;                 // stage 1 [128*36]
    uint32_t* Wss = smem + ROWS * XSTRIDE;// stage 1 [64*36]
    uint32_t* Ys  = smem;                 // stage 2 (aliases stage-1 region) [128*68]
    uint32_t* Ps  = smem + ROWS * YSTRIDE;// stage 2 [64*68]

    const int tid  = threadIdx.x;
    const int warp = tid >> 5;
    const int lane = tid & 31;
    const int gid  = lane >> 2;
    const int ctid = lane & 3;
    const int baseRow = blockIdx.x * ROWS;
    const int bidx = baseRow >> 12;       // 4096 rows per batch

    // ---- stage 1: q = query @ Wq^T ----
    float acc[8][4] = {};
    proj64(query, Wq, baseRow, Xs, Wss, acc);

    // epilogue: sigmoid(q + bq) * weights -> Ys (tf32)
#pragma unroll
    for (int nt = 0; nt < 8; nt++) {
        const int col = nt * 8 + 2 * ctid;
        const float b0 = bq[col], b1 = bq[col + 1];
        const float w0 = g_w[bidx * HIDDEN + col], w1 = g_w[bidx * HIDDEN + col + 1];
        const int r = warp * 16 + gid;
        float q0 = acc[nt][0] + b0, q1 = acc[nt][1] + b1;
        float q2 = acc[nt][2] + b0, q3 = acc[nt][3] + b1;
        Ys[r * YSTRIDE + col]           = f2tf(w0 / (1.f + __expf(-q0)));
        Ys[r * YSTRIDE + col + 1]       = f2tf(w1 / (1.f + __expf(-q1)));
        Ys[(r + 8) * YSTRIDE + col]     = f2tf(w0 / (1.f + __expf(-q2)));
        Ys[(r + 8) * YSTRIDE + col + 1] = f2tf(w1 / (1.f + __expf(-q3)));
    }

    // ---- stage 2: out = Ys @ Wp^T + bp, 16 chunks of 64 output cols ----
    for (int nc = 0; nc < D_MODEL; nc += 64) {
        __syncthreads();   // Ys ready (nc=0) / previous Ps consumers done
        {
            // Stage Wp chunk [64 rows x 64 k-cols] -> Ps. 4096 elems / 256 thr
            // = 4 float4 per thread. Row = tid>>2, k-cols (tid&3)*4 + {0,16,32,48}.
            const int r  = tid >> 2;         // 0..63
            const int c4 = (tid & 3) * 4;    // 0,4,8,12
#pragma unroll
            for (int cc = 0; cc < HIDDEN; cc += 16) {
                const float4 v = *(const float4*)(Wp + (size_t)(nc + r) * HIDDEN + cc + c4);
                uint32_t* dst = Ps + r * YSTRIDE + cc + c4;
                dst[0] = f2tf(v.x); dst[1] = f2tf(v.y); dst[2] = f2tf(v.z); dst[3] = f2tf(v.w);
            }
        }
        __syncthreads();

        float oacc[8][4] = {};
#pragma unroll
        for (int ks = 0; ks < HIDDEN / 8; ks++) {
            uint32_t a[4];
            const uint32_t* yrow = Ys + (warp * 16 + gid) * YSTRIDE + ks * 8 + ctid;
            a[0] = yrow[0];
            a[1] = yrow[8 * YSTRIDE];
            a[2] = yrow[4];
            a[3] = yrow[8 * YSTRIDE + 4];
#pragma unroll
            for (int nt = 0; nt < 8; nt++) {
                uint32_t b[2];
                const uint32_t* prow = Ps + (nt * 8 + gid) * YSTRIDE + ks * 8 + ctid;
                b[0] = prow[0];
                b[1] = prow[4];
                mma8(oacc[nt], a, b);
            }
        }

        // epilogue: + bp, store
#pragma unroll
        for (int nt = 0; nt < 8; nt++) {
            const int col = nc + nt * 8 + 2 * ctid;
            const float b0 = bp[col], b1 = bp[col + 1];
            const size_t r0 = (size_t)(baseRow + warp * 16 + gid);
            *(float2*)(out + r0 * D_MODEL + col) = make_float2(oacc[nt][0] + b0, oacc[nt][1] + b1);
            *(float2*)(out + (r0 + 8) * D_MODEL + col) = make_float2(oacc[nt][2] + b0, oacc[nt][3] + b1);
        }
    }
}

extern "C" void kernel_launch(void* const* d_in, const int* in_sizes, int n_in,
                              void* d_out, int out_size) {
    const float* query = (const float*)d_in[0];
    const float* key_in = (const float*)d_in[1];
    const float* value_in = (const float*)d_in[2];
    const float* Wq = (const float*)d_in[3];
    const float* bq = (const float*)d_in[4];
    const float* Wk = (const float*)d_in[5];
    const float* bk = (const float*)d_in[6];
    const float* Wv = (const float*)d_in[7];
    const float* bv = (const float*)d_in[8];
    const float* Wp = (const float*)d_in[9];
    const float* bp = (const float*)d_in[10];
    float* out = (float*)d_out;

    const int smem3 = (ROWS * YSTRIDE + HIDDEN * YSTRIDE) * 4;  // 52224 B
    cudaFuncSetAttribute(out_kernel, cudaFuncAttributeMaxDynamicSharedMemorySize, smem3);

    kv_proj_kernel<<<512, 256>>>(key_in, value_in, Wk, bk, Wv, bv);
    reduce_kernel<<<512, 256>>>();
    out_kernel<<<256, 256, smem3>>>(query, Wq, bq, Wp, bp, out);
}